// round 9
// baseline (speedup 1.0000x reference)
#include <cuda_runtime.h>
#include <math.h>

#define T_SEQ   4096
#define B_BATCH 4
#define C_EMB   1024
#define H_DIM   64
#define NROWS   (B_BATCH * T_SEQ)   // 16384
#define QB_CNT  (T_SEQ / 64)        // 64 query blocks per batch
#define MAXCH   16                  // 256-key chunks per q-block
#define KSPLIT  4                   // proj k-splits (256 k each)

__device__ float g_Q[NROWS * H_DIM];
__device__ float g_K[NROWS * H_DIM];
__device__ float g_V[NROWS * H_DIM];
// split-K partials: [b][qb][chunk][64 rows][64 cols] and [..][64 rows][m,l]
__device__ float g_Opart[(size_t)B_BATCH * QB_CNT * MAXCH * 64 * 64];
__device__ float g_ml[(size_t)B_BATCH * QB_CNT * MAXCH * 64 * 2];

// ---- helpers -------------------------------------------------------------
__device__ __forceinline__ unsigned f2tf(float f) {
    unsigned r;
    asm("cvt.rna.tf32.f32 %0, %1;" : "=r"(r) : "f"(f));
    return r;
}
__device__ __forceinline__ float tfbits(float f) {
    return __uint_as_float(f2tf(f));
}
__device__ __forceinline__ void mma_tf32(float* d, const unsigned* a, const unsigned* b) {
    asm("mma.sync.aligned.m16n8k8.row.col.f32.tf32.tf32.f32 "
        "{%0,%1,%2,%3}, {%4,%5,%6,%7}, {%8,%9}, {%0,%1,%2,%3};"
        : "+f"(d[0]), "+f"(d[1]), "+f"(d[2]), "+f"(d[3])
        : "r"(a[0]), "r"(a[1]), "r"(a[2]), "r"(a[3]), "r"(b[0]), "r"(b[1]));
}

// ---------------------------------------------------------------------------
// Kernel 0: zero Q/K/V accumulators (proj uses atomicAdd).
// ---------------------------------------------------------------------------
__global__ __launch_bounds__(256) void zero_qkv()
{
    size_t i = (size_t)blockIdx.x * blockDim.x + threadIdx.x;
    float4 z = make_float4(0.f, 0.f, 0.f, 0.f);
    ((float4*)g_Q)[i] = z;
    ((float4*)g_K)[i] = z;
    ((float4*)g_V)[i] = z;
}

// ---------------------------------------------------------------------------
// Kernel 1: QKV projection, split-K (unchanged from R4).
// ---------------------------------------------------------------------------
__global__ __launch_bounds__(256) void proj_kernel(
    const float* __restrict__ x,
    const float* __restrict__ Wq,
    const float* __restrict__ Wk,
    const float* __restrict__ Wv)
{
    const float* W;
    float* outp;
    if (blockIdx.z == 0)      { W = Wq; outp = g_Q; }
    else if (blockIdx.z == 1) { W = Wk; outp = g_K; }
    else                      { W = Wv; outp = g_V; }

    __shared__ float Xs[128][36];
    __shared__ float Ws[32][72];

    const int tid  = threadIdx.x;
    const int warp = tid >> 5;
    const int lane = tid & 31;
    const int g  = lane >> 2;
    const int tg = lane & 3;
    const int row0  = blockIdx.x * 128;
    const int kbase = blockIdx.y * (C_EMB / KSPLIT);

    float acc[8][4];
#pragma unroll
    for (int a = 0; a < 8; a++)
#pragma unroll
        for (int j = 0; j < 4; j++) acc[a][j] = 0.0f;

    float4 px[4], pw[2];
#pragma unroll
    for (int s = 0; s < 4; s++) {
        int idx = tid + s * 256, r = idx >> 3, c4 = idx & 7;
        px[s] = *(const float4*)(x + (size_t)(row0 + r) * C_EMB + kbase + c4 * 4);
    }
#pragma unroll
    for (int s = 0; s < 2; s++) {
        int idx = tid + s * 256, r = idx >> 4, c4 = idx & 15;
        pw[s] = *(const float4*)(W + (size_t)(kbase + r) * H_DIM + c4 * 4);
    }

    for (int c = 0; c < C_EMB / KSPLIT / 32; c++) {
#pragma unroll
        for (int s = 0; s < 4; s++) {
            int idx = tid + s * 256, r = idx >> 3, c4 = idx & 7;
            Xs[r][c4 * 4 + 0] = tfbits(px[s].x);
            Xs[r][c4 * 4 + 1] = tfbits(px[s].y);
            Xs[r][c4 * 4 + 2] = tfbits(px[s].z);
            Xs[r][c4 * 4 + 3] = tfbits(px[s].w);
        }
#pragma unroll
        for (int s = 0; s < 2; s++) {
            int idx = tid + s * 256, r = idx >> 4, c4 = idx & 15;
            Ws[r][c4 * 4 + 0] = tfbits(pw[s].x);
            Ws[r][c4 * 4 + 1] = tfbits(pw[s].y);
            Ws[r][c4 * 4 + 2] = tfbits(pw[s].z);
            Ws[r][c4 * 4 + 3] = tfbits(pw[s].w);
        }
        __syncthreads();

        if (c + 1 < C_EMB / KSPLIT / 32) {
            int k0 = kbase + (c + 1) * 32;
#pragma unroll
            for (int s = 0; s < 4; s++) {
                int idx = tid + s * 256, r = idx >> 3, c4 = idx & 7;
                px[s] = *(const float4*)(x + (size_t)(row0 + r) * C_EMB + k0 + c4 * 4);
            }
#pragma unroll
            for (int s = 0; s < 2; s++) {
                int idx = tid + s * 256, r = idx >> 4, c4 = idx & 15;
                pw[s] = *(const float4*)(W + (size_t)(k0 + r) * H_DIM + c4 * 4);
            }
        }

#pragma unroll
        for (int kc = 0; kc < 32; kc += 8) {
            unsigned a[4];
            a[0] = __float_as_uint(Xs[warp * 16 + g    ][kc + tg    ]);
            a[1] = __float_as_uint(Xs[warp * 16 + g + 8][kc + tg    ]);
            a[2] = __float_as_uint(Xs[warp * 16 + g    ][kc + tg + 4]);
            a[3] = __float_as_uint(Xs[warp * 16 + g + 8][kc + tg + 4]);
#pragma unroll
            for (int at = 0; at < 8; at++) {
                unsigned b[2];
                b[0] = __float_as_uint(Ws[kc + tg    ][at * 8 + g]);
                b[1] = __float_as_uint(Ws[kc + tg + 4][at * 8 + g]);
                mma_tf32(acc[at], a, b);
            }
        }
        __syncthreads();
    }

    const int r0 = row0 + warp * 16 + g;
#pragma unroll
    for (int at = 0; at < 8; at++) {
        int cc = at * 8 + tg * 2;
        atomicAdd(&outp[(size_t)r0 * H_DIM + cc],           acc[at][0]);
        atomicAdd(&outp[(size_t)r0 * H_DIM + cc + 1],       acc[at][1]);
        atomicAdd(&outp[(size_t)(r0 + 8) * H_DIM + cc],     acc[at][2]);
        atomicAdd(&outp[(size_t)(r0 + 8) * H_DIM + cc + 1], acc[at][3]);
    }
}

// ---------------------------------------------------------------------------
// Kernel 2: split-K flash partial.  CTA = (chunk of 256 keys, qb, b).
// Q fragments register-resident; K/V double-buffered; ONE barrier per tile.
// ---------------------------------------------------------------------------
__global__ __launch_bounds__(128) void flash_part_kernel()
{
    const int chunk = blockIdx.x;
    const int qb    = (QB_CNT - 1) - blockIdx.y;   // heavy blocks first
    const int b     = blockIdx.z;
    if (chunk * 4 > qb) return;                    // beyond causal limit

    const int row0 = qb * 64;
    const int nkt  = min(8, (row0 + 64 - chunk * 256 + 31) / 32);

    const float* Qp = g_Q + (size_t)b * T_SEQ * H_DIM;
    const float* Kp = g_K + (size_t)b * T_SEQ * H_DIM;
    const float* Vp = g_V + (size_t)b * T_SEQ * H_DIM;

    __shared__ float Ks[2][32][68];   // double-buffered K (also Q staging)
    __shared__ float Vs[2][32][72];   // double-buffered V
    __shared__ float Ps[64][36];

    const int tid  = threadIdx.x;
    const int warp = tid >> 5;
    const int lane = tid & 31;
    const int g  = lane >> 2;
    const int tg = lane & 3;

    // ---- stage Q through Ks, extract a-frags to registers ----
    for (int i = tid; i < 1024; i += 128) {
        int r = i >> 4, c4 = i & 15;
        float4 v = *(const float4*)(Qp + (size_t)(row0 + r) * H_DIM + c4 * 4);
        float* dst = &Ks[r >> 5][r & 31][c4 * 4];
        dst[0] = tfbits(v.x); dst[1] = tfbits(v.y);
        dst[2] = tfbits(v.z); dst[3] = tfbits(v.w);
    }
    __syncthreads();

    unsigned qa[8][4];
    {
        const int r0 = warp * 16 + g, r1 = r0 + 8;
#pragma unroll
        for (int kc8 = 0; kc8 < 8; kc8++) {
            int kc = kc8 * 8;
            qa[kc8][0] = __float_as_uint(Ks[r0 >> 5][r0 & 31][kc + tg    ]);
            qa[kc8][1] = __float_as_uint(Ks[r1 >> 5][r1 & 31][kc + tg    ]);
            qa[kc8][2] = __float_as_uint(Ks[r0 >> 5][r0 & 31][kc + tg + 4]);
            qa[kc8][3] = __float_as_uint(Ks[r1 >> 5][r1 & 31][kc + tg + 4]);
        }
    }
    __syncthreads();   // all frags extracted before Ks reused for K tiles

    float o[8][4];
#pragma unroll
    for (int a = 0; a < 8; a++)
#pragma unroll
        for (int j = 0; j < 4; j++) o[a][j] = 0.0f;
    float m0 = -1e30f, m1 = -1e30f, l0 = 0.0f, l1 = 0.0f;

    const int r0g = row0 + warp * 16 + g;
    const int r1g = r0g + 8;

    const int ld_r  = tid >> 4;          // 0..7   (row stride 8 per 128 thr)
    const int ld_c4 = tid & 15;          // 0..15  (float4 col)

    float4 pk[4], pv[4];
    // prefetch + store tile 0 into stage 0
    {
        const int key0 = chunk * 256;
#pragma unroll
        for (int s = 0; s < 4; s++) {
            int r = ld_r + s * 8;
            pk[s] = *(const float4*)(Kp + (size_t)(key0 + r) * H_DIM + ld_c4 * 4);
            pv[s] = *(const float4*)(Vp + (size_t)(key0 + r) * H_DIM + ld_c4 * 4);
        }
#pragma unroll
        for (int s = 0; s < 4; s++) {
            int r = ld_r + s * 8;
            float* kd = &Ks[0][r][ld_c4 * 4];
            kd[0] = tfbits(pk[s].x); kd[1] = tfbits(pk[s].y);
            kd[2] = tfbits(pk[s].z); kd[3] = tfbits(pk[s].w);
            float* vd = &Vs[0][r][ld_c4 * 4];
            vd[0] = tfbits(pv[s].x); vd[1] = tfbits(pv[s].y);
            vd[2] = tfbits(pv[s].z); vd[3] = tfbits(pv[s].w);
        }
    }

    for (int kb = 0; kb < nkt; kb++) {
        const int cur  = kb & 1;
        const int key0 = chunk * 256 + kb * 32;
        __syncthreads();   // stage `cur` fully written; prev stage reads done

        // issue next tile's loads early (consumed at end of this iter)
        if (kb + 1 < nkt) {
            const int keyn = key0 + 32;
#pragma unroll
            for (int s = 0; s < 4; s++) {
                int r = ld_r + s * 8;
                pk[s] = *(const float4*)(Kp + (size_t)(keyn + r) * H_DIM + ld_c4 * 4);
                pv[s] = *(const float4*)(Vp + (size_t)(keyn + r) * H_DIM + ld_c4 * 4);
            }
        }

        // ---- S = Q K^T ----
        float s[4][4];
#pragma unroll
        for (int a = 0; a < 4; a++)
#pragma unroll
            for (int j = 0; j < 4; j++) s[a][j] = 0.0f;

#pragma unroll
        for (int kc8 = 0; kc8 < 8; kc8++) {
            int kc = kc8 * 8;
#pragma unroll
            for (int at = 0; at < 4; at++) {
                unsigned bfr[2];
                bfr[0] = __float_as_uint(Ks[cur][at * 8 + g][kc + tg    ]);
                bfr[1] = __float_as_uint(Ks[cur][at * 8 + g][kc + tg + 4]);
                mma_tf32(s[at], qa[kc8], bfr);
            }
        }

        // ---- scale + causal mask ----
        const bool diag = (key0 + 31 > row0);
#pragma unroll
        for (int at = 0; at < 4; at++) {
            int c0 = key0 + at * 8 + tg * 2;
            s[at][0] *= 0.125f; s[at][1] *= 0.125f;
            s[at][2] *= 0.125f; s[at][3] *= 0.125f;
            if (diag) {
                if (c0     > r0g) s[at][0] = -1e30f;
                if (c0 + 1 > r0g) s[at][1] = -1e30f;
                if (c0     > r1g) s[at][2] = -1e30f;
                if (c0 + 1 > r1g) s[at][3] = -1e30f;
            }
        }

        // ---- online softmax ----
        float tm0 = -1e30f, tm1 = -1e30f;
#pragma unroll
        for (int at = 0; at < 4; at++) {
            tm0 = fmaxf(tm0, fmaxf(s[at][0], s[at][1]));
            tm1 = fmaxf(tm1, fmaxf(s[at][2], s[at][3]));
        }
        tm0 = fmaxf(tm0, __shfl_xor_sync(0xffffffffu, tm0, 1));
        tm0 = fmaxf(tm0, __shfl_xor_sync(0xffffffffu, tm0, 2));
        tm1 = fmaxf(tm1, __shfl_xor_sync(0xffffffffu, tm1, 1));
        tm1 = fmaxf(tm1, __shfl_xor_sync(0xffffffffu, tm1, 2));

        float nm0 = fmaxf(m0, tm0), nm1 = fmaxf(m1, tm1);
        float al0 = __expf(m0 - nm0), al1 = __expf(m1 - nm1);
        m0 = nm0; m1 = nm1;

        float tl0 = 0.0f, tl1 = 0.0f;
#pragma unroll
        for (int at = 0; at < 4; at++) {
            s[at][0] = __expf(s[at][0] - nm0);
            s[at][1] = __expf(s[at][1] - nm0);
            s[at][2] = __expf(s[at][2] - nm1);
            s[at][3] = __expf(s[at][3] - nm1);
            tl0 += s[at][0] + s[at][1];
            tl1 += s[at][2] + s[at][3];
        }
        tl0 += __shfl_xor_sync(0xffffffffu, tl0, 1);
        tl0 += __shfl_xor_sync(0xffffffffu, tl0, 2);
        tl1 += __shfl_xor_sync(0xffffffffu, tl1, 1);
        tl1 += __shfl_xor_sync(0xffffffffu, tl1, 2);
        l0 = l0 * al0 + tl0;
        l1 = l1 * al1 + tl1;

#pragma unroll
        for (int at = 0; at < 8; at++) {
            o[at][0] *= al0; o[at][1] *= al0;
            o[at][2] *= al1; o[at][3] *= al1;
        }

#pragma unroll
        for (int at = 0; at < 4; at++) {
            int c = at * 8 + tg * 2;
            Ps[warp * 16 + g    ][c    ] = tfbits(s[at][0]);
            Ps[warp * 16 + g    ][c + 1] = tfbits(s[at][1]);
            Ps[warp * 16 + g + 8][c    ] = tfbits(s[at][2]);
            Ps[warp * 16 + g + 8][c + 1] = tfbits(s[at][3]);
        }
        __syncwarp();

        // ---- O += P V ----
#pragma unroll
        for (int kc = 0; kc < 32; kc += 8) {
            unsigned a[4];
            a[0] = __float_as_uint(Ps[warp * 16 + g    ][kc + tg    ]);
            a[1] = __float_as_uint(Ps[warp * 16 + g + 8][kc + tg    ]);
            a[2] = __float_as_uint(Ps[warp * 16 + g    ][kc + tg + 4]);
            a[3] = __float_as_uint(Ps[warp * 16 + g + 8][kc + tg + 4]);
#pragma unroll
            for (int at = 0; at < 8; at++) {
                unsigned bfr[2];
                bfr[0] = __float_as_uint(Vs[cur][kc + tg    ][at * 8 + g]);
                bfr[1] = __float_as_uint(Vs[cur][kc + tg + 4][at * 8 + g]);
                mma_tf32(o[at], a, bfr);
            }
        }

        // store prefetched tile into the other stage (read next iter)
        if (kb + 1 < nkt) {
            const int nxt = 1 - cur;
#pragma unroll
            for (int s = 0; s < 4; s++) {
                int r = ld_r + s * 8;
                float* kd = &Ks[nxt][r][ld_c4 * 4];
                kd[0] = tfbits(pk[s].x); kd[1] = tfbits(pk[s].y);
                kd[2] = tfbits(pk[s].z); kd[3] = tfbits(pk[s].w);
                float* vd = &Vs[nxt][r][ld_c4 * 4];
                vd[0] = tfbits(pv[s].x); vd[1] = tfbits(pv[s].y);
                vd[2] = tfbits(pv[s].z); vd[3] = tfbits(pv[s].w);
            }
        }
    }

    // ---- write partial (unnormalized O, m, l) ----
    const size_t pidx = ((size_t)(b * QB_CNT + qb) * MAXCH + chunk);
    float* Op = g_Opart + pidx * 64 * 64;
    float* mlp = g_ml + pidx * 64 * 2;

    const int lr0 = warp * 16 + g;
#pragma unroll
    for (int at = 0; at < 8; at++) {
        int c = at * 8 + tg * 2;
        *(float2*)(Op + (size_t)lr0 * 64 + c)       = make_float2(o[at][0], o[at][1]);
        *(float2*)(Op + (size_t)(lr0 + 8) * 64 + c) = make_float2(o[at][2], o[at][3]);
    }
    if (tg == 0) {
        mlp[lr0 * 2 + 0] = m0;  mlp[lr0 * 2 + 1] = l0;
        mlp[(lr0 + 8) * 2 + 0] = m1;  mlp[(lr0 + 8) * 2 + 1] = l1;
    }
}

// ---------------------------------------------------------------------------
// Kernel 3: combine partials.  Block (64 rows, 16 col-segments of 4).
// ---------------------------------------------------------------------------
__global__ __launch_bounds__(1024) void combine_kernel(float* __restrict__ out)
{
    const int qb = blockIdx.x;
    const int b  = blockIdx.y;
    const int row = threadIdx.x;       // 0..63
    const int cs  = threadIdx.y;       // 0..15
    const int nc  = qb / 4 + 1;

    const size_t base = (size_t)(b * QB_CNT + qb) * MAXCH;

    float M = -1e30f;
    for (int c = 0; c < nc; c++)
        M = fmaxf(M, g_ml[(base + c) * 128 + row * 2 + 0]);

    float L = 0.0f;
    float acc0 = 0.f, acc1 = 0.f, acc2 = 0.f, acc3 = 0.f;
    for (int c = 0; c < nc; c++) {
        float m = g_ml[(base + c) * 128 + row * 2 + 0];
        float l = g_ml[(base + c) * 128 + row * 2 + 1];
        float w = __expf(m - M);
        L += w * l;
        float4 v = *(const float4*)(g_Opart + (base + c) * 4096 +
                                    (size_t)row * 64 + cs * 4);
        acc0 += w * v.x; acc1 += w * v.y; acc2 += w * v.z; acc3 += w * v.w;
    }

    float inv = 1.0f / L;
    float* op = out + (size_t)b * T_SEQ * H_DIM + (size_t)(qb * 64 + row) * H_DIM + cs * 4;
    *(float4*)op = make_float4(acc0 * inv, acc1 * inv, acc2 * inv, acc3 * inv);
}

// ---------------------------------------------------------------------------
extern "C" void kernel_launch(void* const* d_in, const int* in_sizes, int n_in,
                              void* d_out, int out_size)
{
    const float* x  = (const float*)d_in[0];
    const float* Wq = (const float*)d_in[1];
    const float* Wk = (const float*)d_in[2];
    const float* Wv = (const float*)d_in[3];
    float* out = (float*)d_out;

    zero_qkv<<<NROWS * H_DIM / 4 / 256, 256>>>();

    dim3 g1(NROWS / 128, KSPLIT, 3);
    proj_kernel<<<g1, 256>>>(x, Wq, Wk, Wv);

    dim3 g2(MAXCH, QB_CNT, B_BATCH);
    flash_part_kernel<<<g2, 128>>>();

    dim3 g3(QB_CNT, B_BATCH);
    combine_kernel<<<g3, dim3(64, 16)>>>(out);
}